// round 4
// baseline (speedup 1.0000x reference)
#include <cuda_runtime.h>

// IDWT1D (Haar synthesis) — 2-tap banded A collapses to a streaming butterfly.
//
//   out[b,2i  ,c] = A[0,0]*x[b,i,c] + A[M,0]*x[b,i,C+c]
//   out[b,2i+1,c] = A[0,1]*x[b,i,c] + A[M,1]*x[b,i,C+c]
//
// Input row (b,i) = 32 contiguous floats [approx16|detail16] at flat offset
// (b*M+i)*32; output rows (b,2i),(b,2i+1) occupy the SAME 32-float span.
//
// R3 finding: 1 float4-pair per thread was latency-bound (issue 39%, all pipes
// <35%). This version: ONE FULL ROW per thread = 8 front-batched LDG.128
// (MLP_p1=8) + 32 FFMA + 8 STG.128, 4x fewer threads, 4x the in-flight loads.

__global__ void __launch_bounds__(256)
idwt_haar_row_kernel(const float* __restrict__ x,
                     const float* __restrict__ A,
                     float* __restrict__ out,
                     long long n_rows,          // B*M total rows
                     long long highpass_row)    // M*N: flat index of A[M,0]
{
    // Filter taps (uniform broadcast loads).
    const float h00 = __ldg(&A[0]);                 // A[0,0]
    const float h01 = __ldg(&A[1]);                 // A[0,1]
    const float h10 = __ldg(&A[highpass_row + 0]);  // A[M,0]
    const float h11 = __ldg(&A[highpass_row + 1]);  // A[M,1]

    const float4* __restrict__ xin = reinterpret_cast<const float4*>(x);
    float4* __restrict__       o   = reinterpret_cast<float4*>(out);

    const long long stride = (long long)gridDim.x * blockDim.x;

    for (long long row = (long long)blockIdx.x * blockDim.x + threadIdx.x;
         row < n_rows; row += stride)
    {
        const long long base = row * 8;   // 8 float4 per 32-float row

        // Front-batch all 8 loads of the row (approx half + detail half)
        float4 a[4], d[4];
        #pragma unroll
        for (int t = 0; t < 4; t++) a[t] = xin[base + t];
        #pragma unroll
        for (int t = 0; t < 4; t++) d[t] = xin[base + 4 + t];

        // Butterfly
        float4 even[4], odd[4];
        #pragma unroll
        for (int t = 0; t < 4; t++) {
            even[t].x = h00 * a[t].x + h10 * d[t].x;
            even[t].y = h00 * a[t].y + h10 * d[t].y;
            even[t].z = h00 * a[t].z + h10 * d[t].z;
            even[t].w = h00 * a[t].w + h10 * d[t].w;

            odd[t].x  = h01 * a[t].x + h11 * d[t].x;
            odd[t].y  = h01 * a[t].y + h11 * d[t].y;
            odd[t].z  = h01 * a[t].z + h11 * d[t].z;
            odd[t].w  = h01 * a[t].w + h11 * d[t].w;
        }

        // 8 stores back to the same span
        #pragma unroll
        for (int t = 0; t < 4; t++) o[base + t]     = even[t];
        #pragma unroll
        for (int t = 0; t < 4; t++) o[base + 4 + t] = odd[t];
    }
}

extern "C" void kernel_launch(void* const* d_in, const int* in_sizes, int n_in,
                              void* d_out, int out_size)
{
    const float* x = (const float*)d_in[0];
    const float* A = (const float*)d_in[1];
    float* out     = (float*)d_out;

    // A is (N, N): recover N from its element count (power of two).
    long long a_elems = in_sizes[1];
    long long N = 1;
    while (N * N < a_elems) N <<= 1;          // 4096 at default shape
    const long long M = N >> 1;
    const long long highpass_row = M * N;     // flat index of A[M, 0]

    const long long n_rows = (long long)in_sizes[0] / 32;   // B*M = 131072

    const int threads = 256;
    long long blocks64 = (n_rows + threads - 1) / threads;  // 512 at default
    const int blocks = (int)(blocks64 > 1048576 ? 1048576 : blocks64);

    idwt_haar_row_kernel<<<blocks, threads>>>(x, A, out, n_rows, highpass_row);
}

// round 6
// speedup vs baseline: 1.7168x; 1.7168x over previous
#include <cuda_runtime.h>

// IDWT1D (Haar synthesis) — 2-tap banded A collapses to a streaming butterfly.
//
//   out[b,2i  ,c] = A[0,0]*x[b,i,c] + A[M,0]*x[b,i,C+c]
//   out[b,2i+1,c] = A[0,1]*x[b,i,c] + A[M,1]*x[b,i,C+c]
//
// Input row (b,i) = 32 contiguous floats [approx16|detail16]; the two output
// rows occupy the SAME 32-float span. Item = one float4-pair (a,d).
//
// R3: 1 item/thread, MLP 2, occ 70%  -> 7.9us (latency-bound, issue 39%)
// R4: 8 loads/thread but regs=32 -> ptxas serialized, occ 38% -> 14us REGRESSION
// R5/R6: 2 items/thread, 4 consecutive front-batched LDG.128 in ONE basic
//        block (fast path), 262144 threads. In-flight loads = 2x R3.

__global__ void __launch_bounds__(256)
idwt_haar_x2_kernel(const float* __restrict__ x,
                    const float* __restrict__ A,
                    float* __restrict__ out,
                    long long n_items,         // total float4-pairs = B*M*4
                    long long highpass_row)    // M*N: flat index of A[M,0]
{
    const float h00 = __ldg(&A[0]);                 // A[0,0]
    const float h01 = __ldg(&A[1]);                 // A[0,1]
    const float h10 = __ldg(&A[highpass_row + 0]);  // A[M,0]
    const float h11 = __ldg(&A[highpass_row + 1]);  // A[M,1]

    const float4* __restrict__ xin = reinterpret_cast<const float4*>(x);
    float4* __restrict__       o   = reinterpret_cast<float4*>(out);

    const long long gsize = (long long)gridDim.x * blockDim.x;
    const long long it0   = (long long)blockIdx.x * blockDim.x + threadIdx.x;
    const long long it1   = it0 + gsize;

    // item -> address: row = it>>2, slot = it&3; approx at row*8+slot,
    // detail at row*8+4+slot.  row*8+slot = (it & ~3)*2 + (it & 3).
    const long long ap0 = ((it0 & ~3LL) << 1) + (it0 & 3);
    const long long ap1 = ((it1 & ~3LL) << 1) + (it1 & 3);

    if (it1 < n_items) {
        // Fast path (always taken at the default shape: 2*gsize == n_items).
        // Four consecutive LDG.128 in one basic block -> MLP_p1 = 4.
        const float4 a0 = xin[ap0];
        const float4 d0 = xin[ap0 + 4];
        const float4 a1 = xin[ap1];
        const float4 d1 = xin[ap1 + 4];

        float4 e0, o0, e1, o1;
        e0.x = h00 * a0.x + h10 * d0.x;  o0.x = h01 * a0.x + h11 * d0.x;
        e0.y = h00 * a0.y + h10 * d0.y;  o0.y = h01 * a0.y + h11 * d0.y;
        e0.z = h00 * a0.z + h10 * d0.z;  o0.z = h01 * a0.z + h11 * d0.z;
        e0.w = h00 * a0.w + h10 * d0.w;  o0.w = h01 * a0.w + h11 * d0.w;

        e1.x = h00 * a1.x + h10 * d1.x;  o1.x = h01 * a1.x + h11 * d1.x;
        e1.y = h00 * a1.y + h10 * d1.y;  o1.y = h01 * a1.y + h11 * d1.y;
        e1.z = h00 * a1.z + h10 * d1.z;  o1.z = h01 * a1.z + h11 * d1.z;
        e1.w = h00 * a1.w + h10 * d1.w;  o1.w = h01 * a1.w + h11 * d1.w;

        o[ap0]     = e0;
        o[ap0 + 4] = o0;
        o[ap1]     = e1;
        o[ap1 + 4] = o1;
    } else if (it0 < n_items) {
        // Tail: only item 0 valid (not reached at default shape).
        const float4 a0 = xin[ap0];
        const float4 d0 = xin[ap0 + 4];
        float4 e0, o0;
        e0.x = h00 * a0.x + h10 * d0.x;  o0.x = h01 * a0.x + h11 * d0.x;
        e0.y = h00 * a0.y + h10 * d0.y;  o0.y = h01 * a0.y + h11 * d0.y;
        e0.z = h00 * a0.z + h10 * d0.z;  o0.z = h01 * a0.z + h11 * d0.z;
        e0.w = h00 * a0.w + h10 * d0.w;  o0.w = h01 * a0.w + h11 * d0.w;
        o[ap0]     = e0;
        o[ap0 + 4] = o0;
    }
}

extern "C" void kernel_launch(void* const* d_in, const int* in_sizes, int n_in,
                              void* d_out, int out_size)
{
    const float* x = (const float*)d_in[0];
    const float* A = (const float*)d_in[1];
    float* out     = (float*)d_out;

    // A is (N, N): recover N from its element count (power of two).
    long long a_elems = in_sizes[1];
    long long N = 1;
    while (N * N < a_elems) N <<= 1;          // 4096 at default shape
    const long long M = N >> 1;
    const long long highpass_row = M * N;     // flat index of A[M, 0]

    const long long n_items = (long long)in_sizes[0] / 8;   // float4-pairs = 524288

    const int threads = 256;
    // 2 items per thread
    long long blocks64 = (n_items / 2 + threads - 1) / threads;  // 1024 at default
    if (blocks64 < 1) blocks64 = 1;
    const int blocks = (int)(blocks64 > 1048576 ? 1048576 : blocks64);

    idwt_haar_x2_kernel<<<blocks, threads>>>(x, A, out, n_items, highpass_row);
}